// round 9
// baseline (speedup 1.0000x reference)
#include <cuda_runtime.h>
#include <cuda_bf16.h>
#include <cstdint>

// Problem constants
#define BB 8
#define CHN 512
#define HH 80
#define WW 80
#define HW 6400
#define CR 32

// ---------------- device scratch ----------------
__device__ float g_means[2 * BB * 160 * CHN];   // [z][b][p][c]
__device__ float g_yz[2 * BB * CR * 160];       // [z][b][cr][160]
__device__ float g_s[4 * BB * CHN * 80];        // [a][b][o][80]
__device__ float g_wr[CHN * 1024];              // W fragment-order tf32
__device__ int g_cnt_mean, g_cnt_yz, g_cnt_s;   // flow-control counters

// ---------------- helpers ----------------
__device__ __forceinline__ unsigned f2tf32(float x) {
    unsigned u;
    asm("cvt.rna.tf32.f32 %0, %1;" : "=r"(u) : "f"(x));
    return u;
}

__device__ __forceinline__ void mma_tf32(float d[4], const unsigned a0, const unsigned a1,
                                         const unsigned a2, const unsigned a3,
                                         const unsigned b0, const unsigned b1) {
    asm volatile(
        "mma.sync.aligned.m16n8k8.row.col.f32.tf32.tf32.f32 "
        "{%0,%1,%2,%3}, {%4,%5,%6,%7}, {%8,%9}, {%0,%1,%2,%3};\n"
        : "+f"(d[0]), "+f"(d[1]), "+f"(d[2]), "+f"(d[3])
        : "r"(a0), "r"(a1), "r"(a2), "r"(a3), "r"(b0), "r"(b1));
}

#define CP_ASYNC16(dst_u32, src_ptr) \
    asm volatile("cp.async.cg.shared.global [%0], [%1], 16;\n" :: "r"(dst_u32), "l"(src_ptr))
#define CP_COMMIT() asm volatile("cp.async.commit_group;\n" ::)
#define CP_WAIT1()  asm volatile("cp.async.wait_group 1;\n" ::)
#define CP_WAIT0()  asm volatile("cp.async.wait_group 0;\n" ::)

__device__ __forceinline__ void spin_until(const int* cnt, int target) {
    if (threadIdx.x == 0) {
        while (*((volatile int*)cnt) < target) __nanosleep(256);
    }
    __syncthreads();
}
__device__ __forceinline__ void signal(int* cnt) {
    __threadfence();
    __syncthreads();
    if (threadIdx.x == 0) atomicAdd(cnt, 1);
}

// ---------------- kernel 1: W-repack (fragment-order tf32) + counter reset ----------------
__global__ void wrepack_kernel(const float* __restrict__ w) {
    if (blockIdx.x == 0 && threadIdx.x == 0) {
        g_cnt_mean = 0; g_cnt_yz = 0; g_cnt_s = 0;
    }
    const int blk = blockIdx.x;          // o_blk*32 + kt
    const int o_blk = blk >> 5, kt = blk & 31;
    const int tid = threadIdx.x;
    #pragma unroll
    for (int i = 0; i < 4; ++i) {
        const int gid = tid + i * 256;
        const int lane = gid & 31;
        const int mi = (gid >> 5) & 3;
        const int wm = (gid >> 7) & 1;
        const int kk = (gid >> 8) & 3;
        const int R  = o_blk * 128 + wm * 64 + mi * 16 + (lane >> 2);
        const int Ka = kt * 32 + kk * 8 + (lane & 3);
        uint4 o;
        o.x = f2tf32(w[(size_t)R * 1024 + Ka]);
        o.y = f2tf32(w[(size_t)(R + 8) * 1024 + Ka]);
        o.z = f2tf32(w[(size_t)R * 1024 + Ka + 4]);
        o.w = f2tf32(w[(size_t)(R + 8) * 1024 + Ka + 4]);
        reinterpret_cast<uint4*>(g_wr)[(size_t)blk * 1024 + gid] = o;
    }
}

// ---------------- kernel 2: fused mega kernel ----------------
#define MEAN_BLOCKS 128
#define YZ_BLOCKS 32
#define S_BLOCKS 32
#define PRO_BLOCKS 192          // 128 + 32 + 32
#define GEMM_BLOCKS 1600

#define BM 128
#define BN 128
#define BK 32
#define A_STAGE_FLOATS 4096
#define XS_STRIDE 136
#define X_STAGE_FLOATS (BK * XS_STRIDE)   // 4352
#define STAGE_FLOATS (A_STAGE_FLOATS + X_STAGE_FLOATS)  // 8448
#define NSTAGE 3
#define GEMM_SMEM (NSTAGE * STAGE_FLOATS * 4)           // 101376 bytes

__global__ __launch_bounds__(256, 2)
void mega_kernel(const float* __restrict__ rgb, const float* __restrict__ t,
                 const float* __restrict__ w_r1, const float* __restrict__ w_t1,
                 const float* __restrict__ bn_g, const float* __restrict__ bn_b,
                 const float* __restrict__ bn_m, const float* __restrict__ bn_v,
                 const float* __restrict__ w_fh1, const float* __restrict__ w_fw1,
                 const float* __restrict__ w_fh2, const float* __restrict__ w_fw2,
                 float* __restrict__ out) {
    extern __shared__ float dynsmem[];
    const int bid = blockIdx.x;
    const int tid = threadIdx.x;

    if (bid < MEAN_BLOCKS) {
        // ---- mean segment: 64 channel-units each, cp.async double-buffered ----
        float* buf0 = dynsmem;
        float* buf1 = dynsmem + HW;
        auto issue_unit = [&](int j, float* buf) {
            const int unit = bid * 64 + j;
            const int z = unit >> 12, b = (unit >> 9) & 7, c = unit & 511;
            const float* src = (z ? t : rgb) + ((size_t)(b * CHN) + c) * HW;
            for (int i = tid; i < HW / 4; i += 256) {
                unsigned d = (unsigned)__cvta_generic_to_shared(buf + i * 4);
                CP_ASYNC16(d, src + i * 4);
            }
        };
        issue_unit(0, buf0); CP_COMMIT();
        for (int j = 0; j < 64; ++j) {
            float* cur = (j & 1) ? buf1 : buf0;
            if (j + 1 < 64) { issue_unit(j + 1, (j & 1) ? buf0 : buf1); CP_COMMIT(); CP_WAIT1(); }
            else CP_WAIT0();
            __syncthreads();
            const int unit = bid * 64 + j;
            const int z = unit >> 12, b = (unit >> 9) & 7, c = unit & 511;
            float* dst = g_means + (((size_t)z * BB + b) * 160) * CHN + c;
            if (tid < 80) {
                float s = 0.f;
                const float4* r4 = reinterpret_cast<const float4*>(cur + tid * 80);
                #pragma unroll
                for (int w = 0; w < 20; ++w) { float4 v = r4[w]; s += v.x + v.y + v.z + v.w; }
                dst[(size_t)tid * CHN] = s * (1.f / 80.f);
            } else if (tid < 160) {
                const int w = tid - 80;
                float s = 0.f;
                #pragma unroll 8
                for (int h = 0; h < 80; ++h) s += cur[h * 80 + w];
                dst[(size_t)tid * CHN] = s * (1.f / 80.f);
            }
            __syncthreads();
        }
        signal(&g_cnt_mean);

    } else if (bid < MEAN_BLOCKS + YZ_BLOCKS) {
        // ---- yz segment: spin on means, then 10 units each ----
        spin_until(&g_cnt_mean, MEAN_BLOCKS);
        float* w_s = dynsmem;              // 256*33
        float* x_s = dynsmem + 256 * 33;   // 8*256
        const int base = (bid - MEAN_BLOCKS) * 10;
        for (int u = 0; u < 10; ++u) {
            const int unit = base + u;
            const int p0 = (unit % 20) * 8;
            const int b  = (unit / 20) % 8;
            const int z  = unit / 160;
            const float* wsrc = z ? w_t1 : w_r1;
            const float* xbase = g_means + (((size_t)z * BB + b) * 160 + p0) * CHN;
            const int cr = tid & 31;
            const int pl = tid >> 5;
            float acc = 0.f;
            for (int half = 0; half < 2; ++half) {
                const int c0 = half * 256;
                for (int j = tid; j < 32 * 256; j += 256) {
                    const int cc = j & 255, crr = j >> 8;
                    w_s[cc * 33 + crr] = wsrc[crr * CHN + c0 + cc];
                }
                for (int j = tid; j < 8 * 256; j += 256) {
                    const int ppl = j >> 8, cc = j & 255;
                    x_s[ppl * 256 + cc] = xbase[(size_t)ppl * CHN + c0 + cc];
                }
                __syncthreads();
                #pragma unroll 8
                for (int cc = 0; cc < 256; ++cc)
                    acc += w_s[cc * 33 + cr] * x_s[pl * 256 + cc];
                __syncthreads();
            }
            float s = acc;
            if (z == 0) {
                const float sc = bn_g[cr] * rsqrtf(bn_v[cr] + 1e-5f);
                s = s * sc + (bn_b[cr] - bn_m[cr] * sc);
            }
            s = fmaxf(s, 0.f);
            g_yz[(((size_t)z * BB + b) * CR + cr) * 160 + p0 + pl] = s;
        }
        signal(&g_cnt_yz);

    } else if (bid < PRO_BLOCKS) {
        // ---- s segment: spin on yz, then 8 units each ----
        spin_until(&g_cnt_yz, YZ_BLOCKS);
        float* ys  = dynsmem;              // 32*80
        float* wch = dynsmem + CR * 80;    // 64*33
        const int base = (bid - MEAN_BLOCKS - YZ_BLOCKS) * 8;
        for (int u = 0; u < 8; ++u) {
            const int unit = base + u;
            const int a  = unit >> 6;
            const int b  = (unit >> 3) & 7;
            const int oc = unit & 7;
            const float* wp = (a == 0) ? w_fh1 : (a == 1) ? w_fw1 : (a == 2) ? w_fh2 : w_fw2;
            const int z = a >> 1;
            const int off = (a & 1) * 80;
            for (int i = tid; i < CR * 80; i += 256) {
                const int cr = i / 80, p = i % 80;
                ys[cr * 80 + p] = g_yz[(((size_t)z * BB + b) * CR + cr) * 160 + off + p];
            }
            for (int i = tid; i < 64 * 32; i += 256) {
                const int ol = i >> 5, cr = i & 31;
                wch[ol * 33 + cr] = wp[(oc * 64 + ol) * CR + cr];
            }
            __syncthreads();
            const int ol = tid >> 2;
            const int hg = (tid & 3) * 20;
            float* dst = g_s + (((size_t)a * BB + b) * CHN + oc * 64 + ol) * 80;
            #pragma unroll
            for (int j = 0; j < 20; ++j) {
                const int h = hg + j;
                float s = 0.f;
                #pragma unroll
                for (int cr = 0; cr < CR; ++cr) s += wch[ol * 33 + cr] * ys[cr * 80 + h];
                dst[h] = 1.f / (1.f + __expf(-s));
            }
            __syncthreads();
        }
        signal(&g_cnt_s);

    } else {
        // ---- gemm segment (R7 config) ----
        const int gid = bid - PRO_BLOCKS;
        const int px = gid % 50;
        const int rest = gid / 50;
        const int o_blk = rest & 3;
        const int b = rest >> 2;
        const int p0 = px * BN;
        const int lane = tid & 31;
        const int warp = tid >> 5;
        const int wm = warp >> 2;
        const int wn = warp & 3;

        const float* rgbB = rgb + (size_t)b * CHN * HW;
        const float* tB   = t   + (size_t)b * CHN * HW;
        const float* wbase = g_wr + (size_t)o_blk * 32 * A_STAGE_FLOATS;

        float acc[4][4][4];
        #pragma unroll
        for (int i = 0; i < 4; ++i)
            #pragma unroll
            for (int j = 0; j < 4; ++j)
                #pragma unroll
                for (int e = 0; e < 4; ++e) acc[i][j][e] = 0.f;

        auto issue = [&](int stage, int kt) {
            const int k0 = kt * BK;
            const float* xb = (k0 < CHN) ? rgbB : tB;
            const int krow = k0 & (CHN - 1);
            float* As = dynsmem + stage * STAGE_FLOATS;
            float* Xs = As + A_STAGE_FLOATS;
            const float* asrc = wbase + (size_t)kt * A_STAGE_FLOATS;
            #pragma unroll
            for (int ps = 0; ps < 4; ++ps) {
                const int off = (tid + ps * 256) * 4;
                unsigned d = (unsigned)__cvta_generic_to_shared(&As[off]);
                CP_ASYNC16(d, asrc + off);
            }
            #pragma unroll
            for (int ps = 0; ps < 4; ++ps) {
                const int row = (tid >> 5) + ps * 8;
                const int cq  = (tid & 31) * 4;
                unsigned d = (unsigned)__cvta_generic_to_shared(&Xs[row * XS_STRIDE + cq]);
                CP_ASYNC16(d, xb + (size_t)(krow + row) * HW + p0 + cq);
            }
        };

        issue(0, 0); CP_COMMIT();
        issue(1, 1); CP_COMMIT();

        for (int kt = 0; kt < 1024 / BK; ++kt) {
            CP_WAIT1();
            __syncthreads();
            if (kt + 2 < 1024 / BK) issue((kt + 2) % NSTAGE, kt + 2);
            CP_COMMIT();

            const float* As = dynsmem + (kt % NSTAGE) * STAGE_FLOATS;
            const float* Xs = As + A_STAGE_FLOATS;
            const uint4* a4 = reinterpret_cast<const uint4*>(As);

            #pragma unroll
            for (int kk = 0; kk < 4; ++kk) {
                uint4 av[4];
                #pragma unroll
                for (int mi = 0; mi < 4; ++mi)
                    av[mi] = a4[((kk * 2 + wm) * 4 + mi) * 32 + lane];
                unsigned bfr[4][2];
                const int ka = kk * 8 + (lane & 3);
                const int cb = wn * 32 + (lane >> 2);
                #pragma unroll
                for (int ni = 0; ni < 4; ++ni) {
                    const float* bp = &Xs[ka * XS_STRIDE + cb + ni * 8];
                    bfr[ni][0] = f2tf32(bp[0]);
                    bfr[ni][1] = f2tf32(bp[4 * XS_STRIDE]);
                }
                #pragma unroll
                for (int mi = 0; mi < 4; ++mi)
                    #pragma unroll
                    for (int ni = 0; ni < 4; ++ni)
                        mma_tf32(acc[mi][ni], av[mi].x, av[mi].y, av[mi].z, av[mi].w,
                                 bfr[ni][0], bfr[ni][1]);
            }
        }

        // wait for gates, then epilogue
        spin_until(&g_cnt_s, S_BLOCKS);

        const float* sh1 = g_s + (((size_t)0 * BB + b) * CHN) * 80;
        const float* sw1 = g_s + (((size_t)1 * BB + b) * CHN) * 80;
        const float* sh2 = g_s + (((size_t)2 * BB + b) * CHN) * 80;
        const float* sw2 = g_s + (((size_t)3 * BB + b) * CHN) * 80;
        float* outB = out + (size_t)b * CHN * HW;
        const int o0 = o_blk * BM;

        #pragma unroll
        for (int mi = 0; mi < 4; ++mi) {
            const int r = o0 + wm * 64 + mi * 16 + (lane >> 2);
            #pragma unroll
            for (int ni = 0; ni < 4; ++ni) {
                const int pc = p0 + wn * 32 + ni * 8 + 2 * (lane & 3);
                const int h = pc / 80;
                const int w = pc - h * 80;
                #pragma unroll
                for (int half = 0; half < 2; ++half) {
                    const int o = r + half * 8;
                    const float sh1v = sh1[o * 80 + h];
                    const float sh2v = sh2[o * 80 + h];
                    const float g0 = sh1v * sw1[o * 80 + w]     + sh2v * sw2[o * 80 + w];
                    const float g1 = sh1v * sw1[o * 80 + w + 1] + sh2v * sw2[o * 80 + w + 1];
                    float2 v;
                    v.x = acc[mi][ni][half * 2 + 0] * g0;
                    v.y = acc[mi][ni][half * 2 + 1] * g1;
                    *reinterpret_cast<float2*>(outB + (size_t)o * HW + pc) = v;
                }
            }
        }
    }
}

// ---------------- launch ----------------
extern "C" void kernel_launch(void* const* d_in, const int* in_sizes, int n_in,
                              void* d_out, int out_size) {
    const float* rgb    = (const float*)d_in[0];
    const float* t      = (const float*)d_in[1];
    const float* w_fuse = (const float*)d_in[2];
    const float* w_r1   = (const float*)d_in[3];
    const float* w_t1   = (const float*)d_in[4];
    const float* w_fh1  = (const float*)d_in[5];
    const float* w_fw1  = (const float*)d_in[6];
    const float* w_fh2  = (const float*)d_in[7];
    const float* w_fw2  = (const float*)d_in[8];
    const float* bn_g   = (const float*)d_in[9];
    const float* bn_b   = (const float*)d_in[10];
    const float* bn_m   = (const float*)d_in[11];
    const float* bn_v   = (const float*)d_in[12];
    float* out = (float*)d_out;

    cudaFuncSetAttribute(mega_kernel, cudaFuncAttributeMaxDynamicSharedMemorySize, GEMM_SMEM);

    wrepack_kernel<<<128, 256>>>(w_fuse);
    mega_kernel<<<PRO_BLOCKS + GEMM_BLOCKS, 256, GEMM_SMEM>>>(
        rgb, t, w_r1, w_t1, bn_g, bn_b, bn_m, bn_v,
        w_fh1, w_fw1, w_fh2, w_fw2, out);
}